// round 12
// baseline (speedup 1.0000x reference)
#include <cuda_runtime.h>
#include <cuda_bf16.h>
#include <cstdint>

#define SS     2048
#define DD     128
#define NHEAD  32
#define SCALE  0.08838834764831845f
#define CH     32          // k-chunk width
#define SA2    40          // plane row stride (bf16 elems) = 80B, ldmatrix conflict-free
#define PLANE_B (128 * SA2 * 2)          // 10240 B per plane

// pre-split operand planes (hi/lo bf16) in device scratch
__device__ __nv_bfloat16 g_Qhi[(size_t)NHEAD * SS * DD];
__device__ __nv_bfloat16 g_Qlo[(size_t)NHEAD * SS * DD];
__device__ __nv_bfloat16 g_Khi[(size_t)NHEAD * SS * DD];
__device__ __nv_bfloat16 g_Klo[(size_t)NHEAD * SS * DD];
__device__ __nv_bfloat16 g_Vthi[(size_t)NHEAD * DD * SS];   // [head][d][k]
__device__ __nv_bfloat16 g_Vtlo[(size_t)NHEAD * DD * SS];
// per-row partial sums of exp(scores): [head][row][colCTA]
__device__ float g_part[(size_t)NHEAD * SS * 16];

// ---------------------------------------------------------------------------
// helpers
// ---------------------------------------------------------------------------
__device__ __forceinline__ unsigned smem_u32(const void* p)
{
    return (unsigned)__cvta_generic_to_shared(p);
}

__device__ __forceinline__ void split_pack(float f0, float f1,
                                           unsigned& hi, unsigned& lo)
{
    __nv_bfloat162 h;
    h.x = __float2bfloat16(f0);
    h.y = __float2bfloat16(f1);
    __nv_bfloat162 l;
    l.x = __float2bfloat16(f0 - __bfloat162float(h.x));
    l.y = __float2bfloat16(f1 - __bfloat162float(h.y));
    hi = *reinterpret_cast<unsigned*>(&h);
    lo = *reinterpret_cast<unsigned*>(&l);
}

__device__ __forceinline__ void ldsm_x4(unsigned& r0, unsigned& r1,
                                        unsigned& r2, unsigned& r3,
                                        unsigned addr)
{
    asm volatile("ldmatrix.sync.aligned.m8n8.x4.shared.b16 {%0,%1,%2,%3}, [%4];"
                 : "=r"(r0), "=r"(r1), "=r"(r2), "=r"(r3) : "r"(addr));
}

__device__ __forceinline__ void mma_bf16(float* c, const unsigned* a,
                                         const unsigned* b)
{
    asm volatile(
        "mma.sync.aligned.m16n8k16.row.col.f32.bf16.bf16.f32 "
        "{%0,%1,%2,%3}, {%4,%5,%6,%7}, {%8,%9}, {%0,%1,%2,%3};"
        : "+f"(c[0]), "+f"(c[1]), "+f"(c[2]), "+f"(c[3])
        : "r"(a[0]), "r"(a[1]), "r"(a[2]), "r"(a[3]),
          "r"(b[0]), "r"(b[1]));
}

#define CP16(dst, src) \
    asm volatile("cp.async.cg.shared.global [%0], [%1], 16;" :: "r"(dst), "l"(src))
#define CP_COMMIT  asm volatile("cp.async.commit_group;")
#define CP_WAIT1   asm volatile("cp.async.wait_group 1;")
#define CP_WAIT0   asm volatile("cp.async.wait_group 0;")

// lane offsets (bytes) for ldmatrix fragments inside a [128][SA2] plane
struct LaneOff { int a[4]; int b[2]; };

__device__ __forceinline__ LaneOff make_off(int warp, int lane)
{
    const int wr = (warp >> 2) * 64;
    const int wc = (warp & 3) * 32;
    const int rA = (lane & 7) + ((lane >> 3) & 1) * 8;
    const int cA = (lane >> 4) * 8;
    const int rB = (lane & 7) + (lane >> 4) * 8;
    const int cB = ((lane >> 3) & 1) * 8;
    LaneOff o;
#pragma unroll
    for (int mi = 0; mi < 4; mi++) o.a[mi] = ((wr + mi * 16 + rA) * SA2 + cA) * 2;
#pragma unroll
    for (int np = 0; np < 2; np++) o.b[np] = ((wc + np * 16 + rB) * SA2 + cB) * 2;
    return o;
}

// one 32-wide k-chunk of MMAs (2 k16-steps), 3-term split
__device__ __forceinline__ void mma_chunk(
    unsigned aHiB, unsigned aLoB, unsigned bHiB, unsigned bLoB,
    const LaneOff& o, float acc[4][4][4])
{
#pragma unroll
    for (int ks = 0; ks < 2; ks++) {
        const unsigned off = ks * 32;
        unsigned bh[4][2], bl[4][2];
        ldsm_x4(bh[0][0], bh[0][1], bh[1][0], bh[1][1], bHiB + o.b[0] + off);
        ldsm_x4(bh[2][0], bh[2][1], bh[3][0], bh[3][1], bHiB + o.b[1] + off);
        ldsm_x4(bl[0][0], bl[0][1], bl[1][0], bl[1][1], bLoB + o.b[0] + off);
        ldsm_x4(bl[2][0], bl[2][1], bl[3][0], bl[3][1], bLoB + o.b[1] + off);
#pragma unroll
        for (int mi = 0; mi < 4; mi++) {
            unsigned ah[4], al[4];
            ldsm_x4(ah[0], ah[1], ah[2], ah[3], aHiB + o.a[mi] + off);
            ldsm_x4(al[0], al[1], al[2], al[3], aLoB + o.a[mi] + off);
#pragma unroll
            for (int ni = 0; ni < 4; ni++) {
                mma_bf16(acc[mi][ni], ah, bh[ni]);
                mma_bf16(acc[mi][ni], ah, bl[ni]);
                mma_bf16(acc[mi][ni], al, bh[ni]);
            }
        }
    }
}

// ---------------------------------------------------------------------------
// merged prep kernel: blocks [0,8192) split Q,K ; blocks [8192,16384) split V
// ---------------------------------------------------------------------------
__global__ __launch_bounds__(256) void prep_all(
    const float* __restrict__ Q, const float* __restrict__ K,
    const float* __restrict__ V)
{
    __shared__ float T[32][33];
    if (blockIdx.x < 8192) {
        size_t idx = (size_t)blockIdx.x * 256 + threadIdx.x;
        float4 qv = ((const float4*)Q)[idx];
        unsigned h0, l0, h1, l1;
        split_pack(qv.x * SCALE, qv.y * SCALE, h0, l0);
        split_pack(qv.z * SCALE, qv.w * SCALE, h1, l1);
        ((uint2*)g_Qhi)[idx] = make_uint2(h0, h1);
        ((uint2*)g_Qlo)[idx] = make_uint2(l0, l1);
        float4 kv = ((const float4*)K)[idx];
        split_pack(kv.x, kv.y, h0, l0);
        split_pack(kv.z, kv.w, h1, l1);
        ((uint2*)g_Khi)[idx] = make_uint2(h0, h1);
        ((uint2*)g_Klo)[idx] = make_uint2(l0, l1);
    } else {
        int b    = blockIdx.x - 8192;
        int k0   = (b & 63) * 32;
        int d0   = ((b >> 6) & 3) * 32;
        int head = b >> 8;
        const int tid = threadIdx.x;
        const float* v = V + (size_t)head * SS * DD;
#pragma unroll
        for (int p = 0; p < 4; p++) {
            int kl = (tid >> 5) + p * 8;
            int dl = tid & 31;
            T[dl][kl] = v[(size_t)(k0 + kl) * DD + d0 + dl];
        }
        __syncthreads();
#pragma unroll
        for (int p = 0; p < 4; p++) {
            int dl = (tid >> 5) + p * 8;
            int kl = tid & 31;
            float f = T[dl][kl];
            __nv_bfloat16 h = __float2bfloat16(f);
            __nv_bfloat16 l = __float2bfloat16(f - __bfloat162float(h));
            size_t out = ((size_t)head * DD + d0 + dl) * SS + k0 + kl;
            g_Vthi[out] = h;
            g_Vtlo[out] = l;
        }
    }
}

// ---------------------------------------------------------------------------
// Kernel A: W = exp(Q' @ K^T), per-row partial sums -> g_part.
// 1 CTA/SM, 256 regs/thread -> ptxas can pipeline LDSM with HMMA.
// ---------------------------------------------------------------------------
#define QK_STAGE_B (4 * PLANE_B)
#define QK_SMEM    (2 * QK_STAGE_B)

__global__ __launch_bounds__(256, 1) void qk_kernel(float* __restrict__ W)
{
    extern __shared__ __nv_bfloat16 smb[];
    __shared__ float part_sm[128 * 4];
    const unsigned base = smem_u32(smb);

    const int tid  = threadIdx.x;
    const int lane = tid & 31;
    const int warp = tid >> 5;
    const int head = blockIdx.z;
    const int rowBase = blockIdx.y * 128;
    const int colBase = blockIdx.x * 128;

    float* w = W + (size_t)head * SS * SS;

    const size_t qoff = ((size_t)head * SS + rowBase) * DD;
    const size_t koff = ((size_t)head * SS + colBase) * DD;
    const __nv_bfloat16* srcP[8];
    unsigned dstOff[8];
#pragma unroll
    for (int i = 0; i < 8; i++) {
        int idx = tid + i * 256;
        int seg = idx & 3;
        int r   = (idx >> 2) & 127;
        int pl  = idx >> 9;
        const __nv_bfloat16* bp =
            pl == 0 ? g_Qhi + qoff : pl == 1 ? g_Qlo + qoff :
            pl == 2 ? g_Khi + koff : g_Klo + koff;
        srcP[i]   = bp + (size_t)r * DD + seg * 8;
        dstOff[i] = pl * PLANE_B + r * (SA2 * 2) + seg * 16;
    }

    const LaneOff lo = make_off(warp, lane);

    float acc[4][4][4];
#pragma unroll
    for (int mi = 0; mi < 4; mi++)
#pragma unroll
        for (int ni = 0; ni < 4; ni++)
#pragma unroll
            for (int t = 0; t < 4; t++) acc[mi][ni][t] = 0.0f;

#pragma unroll
    for (int i = 0; i < 8; i++)
        CP16(base + dstOff[i], srcP[i]);
    CP_COMMIT;

    const int NCH = DD / CH;   // 4
#pragma unroll
    for (int c = 0; c < NCH; c++) {
        __syncthreads();
        if (c + 1 < NCH) {
            const unsigned sb = base + ((c + 1) & 1) * QK_STAGE_B;
#pragma unroll
            for (int i = 0; i < 8; i++)
                CP16(sb + dstOff[i], srcP[i] + (c + 1) * CH);
            CP_COMMIT;
            CP_WAIT1;
        } else {
            CP_WAIT0;
        }
        __syncthreads();

        const unsigned st = base + (c & 1) * QK_STAGE_B;
        mma_chunk(st, st + PLANE_B, st + 2 * PLANE_B, st + 3 * PLANE_B, lo, acc);
    }

    // epilogue: exp in place, row-sum reduce, write W and partial sums
    const int wr = (warp >> 2) * 64;
    const int wc = (warp & 3) * 32;
    const int gg = lane >> 2;
    const int cq = (lane & 3) * 2;

#pragma unroll
    for (int mi = 0; mi < 4; mi++) {
        float s0 = 0.0f, s1 = 0.0f;
#pragma unroll
        for (int ni = 0; ni < 4; ni++) {
            acc[mi][ni][0] = __expf(acc[mi][ni][0]);
            acc[mi][ni][1] = __expf(acc[mi][ni][1]);
            acc[mi][ni][2] = __expf(acc[mi][ni][2]);
            acc[mi][ni][3] = __expf(acc[mi][ni][3]);
            s0 += acc[mi][ni][0] + acc[mi][ni][1];
            s1 += acc[mi][ni][2] + acc[mi][ni][3];
        }
        s0 += __shfl_xor_sync(0xffffffffu, s0, 1);
        s0 += __shfl_xor_sync(0xffffffffu, s0, 2);
        s1 += __shfl_xor_sync(0xffffffffu, s1, 1);
        s1 += __shfl_xor_sync(0xffffffffu, s1, 2);
        if ((lane & 3) == 0) {
            part_sm[(wr + mi * 16 + gg) * 4 + (warp & 3)]     = s0;
            part_sm[(wr + mi * 16 + gg + 8) * 4 + (warp & 3)] = s1;
        }
    }

#pragma unroll
    for (int mi = 0; mi < 4; mi++) {
#pragma unroll
        for (int ni = 0; ni < 4; ni++) {
            int row = rowBase + wr + mi * 16 + gg;
            int col = colBase + wc + ni * 8 + cq;
            float2 v0 = { acc[mi][ni][0], acc[mi][ni][1] };
            float2 v1 = { acc[mi][ni][2], acc[mi][ni][3] };
            *(float2*)(w + (size_t)row * SS + col)       = v0;
            *(float2*)(w + (size_t)(row + 8) * SS + col) = v1;
        }
    }

    __syncthreads();
    if (tid < 128) {
        float s = part_sm[tid * 4 + 0] + part_sm[tid * 4 + 1]
                + part_sm[tid * 4 + 2] + part_sm[tid * 4 + 3];
        g_part[((size_t)head * SS + rowBase + tid) * 16 + blockIdx.x] = s;
    }
}

// ---------------------------------------------------------------------------
// Kernel C: O = P @ V ; normalizes W in place while reading it.
// 1 CTA/SM, 256 regs: P LDG prefetch depth 2 (register double-buffer),
// warp-private V (no V barrier), 1 __syncthreads per chunk.
// ---------------------------------------------------------------------------
#define PV_PPL   0
#define PV_PBUF  (2 * PLANE_B)          // one buf = hi+lo
#define PV_VST   (2 * PV_PBUF)          // 40960
#define PV_VSTG  (2 * PLANE_B)
#define PV_SMEM  (PV_VST + 2 * PV_VSTG) // 81920

__global__ __launch_bounds__(256, 1) void pv_kernel(
    float* P, float* __restrict__ O)
{
    extern __shared__ __nv_bfloat16 smb[];
    const unsigned base = smem_u32(smb);

    const int tid  = threadIdx.x;
    const int lane = tid & 31;
    const int warp = tid >> 5;
    const int head = blockIdx.y;
    const int rowBase = blockIdx.x * 128;
    const int wc   = (warp & 3) * 32;   // this warp's V d-rows

    float* p = P + (size_t)head * SS * SS;
    float* o = O + (size_t)head * SS * DD;

    // P LDG/STG mapping + per-row inverse sums
    float* pptr[4];
    unsigned pElem[4];
    float inv[4];
#pragma unroll
    for (int i = 0; i < 4; i++) {
        int idx = tid + i * 256;
        int seg = idx & 7;
        int r   = idx >> 3;
        pptr[i]  = p + (size_t)(rowBase + r) * SS + seg * 4;
        pElem[i] = r * SA2 + seg * 4;
        const float4* gp = (const float4*)&g_part[((size_t)head * SS + rowBase + r) * 16];
        float4 a = gp[0], b = gp[1], c = gp[2], d = gp[3];
        float s = ((a.x + a.y) + (a.z + a.w)) + ((b.x + b.y) + (b.z + b.w))
                + ((c.x + c.y) + (c.z + c.w)) + ((d.x + d.y) + (d.z + d.w));
        inv[i] = 1.0f / s;
    }

    // warp-private V base pointers
    const __nv_bfloat16* vhi = g_Vthi + (size_t)head * DD * SS;
    const __nv_bfloat16* vlo = g_Vtlo + (size_t)head * DD * SS;

    auto load_v = [&](int c, int stage) {
        const unsigned vb = base + PV_VST + stage * PV_VSTG;
#pragma unroll
        for (int j = 0; j < 8; j++) {
            int idx = lane + 32 * j;
            int seg = idx & 3;
            int r   = (idx >> 2) & 31;
            int pl  = idx >> 7;
            const __nv_bfloat16* s =
                (pl ? vlo : vhi) + (size_t)(wc + r) * SS + c * CH + seg * 8;
            unsigned d = vb + pl * PLANE_B + (wc + r) * (SA2 * 2) + seg * 16;
            CP16(d, s);
        }
        CP_COMMIT;
    };

    // split a register-held raw P chunk into plane buf, normalize + write back
    auto split_to = [&](const float4* n4, int chunk, int buf) {
        __nv_bfloat16* phi = smb + (PV_PPL + buf * PV_PBUF) / 2;
        __nv_bfloat16* plo = phi + PLANE_B / 2;
#pragma unroll
        for (int i = 0; i < 4; i++) {
            float4 f = n4[i];
            f.x *= inv[i]; f.y *= inv[i]; f.z *= inv[i]; f.w *= inv[i];
            *(float4*)(pptr[i] + chunk * CH) = f;   // normalized W back to gmem
            unsigned h0, l0, h1, l1;
            split_pack(f.x, f.y, h0, l0);
            split_pack(f.z, f.w, h1, l1);
            *(uint2*)(phi + pElem[i]) = make_uint2(h0, h1);
            *(uint2*)(plo + pElem[i]) = make_uint2(l0, l1);
        }
    };

    const LaneOff lof = make_off(warp, lane);

    float acc[4][4][4];
#pragma unroll
    for (int mi = 0; mi < 4; mi++)
#pragma unroll
        for (int ni = 0; ni < 4; ni++)
#pragma unroll
            for (int t = 0; t < 4; t++) acc[mi][ni][t] = 0.0f;

    // prologue: V chunk0; P chunk0 load+split -> buf0; P chunk1 -> reg buf 1
    load_v(0, 0);
    float4 nreg[2][4];
    {
        float4 c0[4];
#pragma unroll
        for (int i = 0; i < 4; i++) c0[i] = *(const float4*)(pptr[i]);
        split_to(c0, 0, 0);
    }
#pragma unroll
    for (int i = 0; i < 4; i++) nreg[1][i] = *(const float4*)(pptr[i] + CH);
    __syncthreads();   // buf0 visible

    const int NCH = SS / CH;   // 64
    for (int c = 0; c < NCH; c++) {
        // V chunk c+1 prefetch (own rows), then in-warp wait for chunk c
        if (c + 1 < NCH) {
            load_v(c + 1, (c + 1) & 1);
            CP_WAIT1;
        } else {
            CP_WAIT0;
        }

        // P chunk c+2 LDG (depth-2 prefetch, hides DRAM latency under 2 MMAs)
        if (c + 2 < NCH) {
#pragma unroll
            for (int i = 0; i < 4; i++)
                nreg[c & 1][i] = *(const float4*)(pptr[i] + (c + 2) * CH);
        }

        const unsigned pb = base + PV_PPL + (c & 1) * PV_PBUF;
        const unsigned vb = base + PV_VST + (c & 1) * PV_VSTG;
        mma_chunk(pb, pb + PLANE_B, vb, vb + PLANE_B, lof, acc);

        // split chunk c+1 (loaded at iter c-1) into the other plane buf
        if (c + 1 < NCH)
            split_to(nreg[(c + 1) & 1], c + 1, (c + 1) & 1);

        __syncthreads();   // one barrier per chunk
    }

    // epilogue
    const int wr = (warp >> 2) * 64;
    const int gg = lane >> 2;
    const int cq = (lane & 3) * 2;
#pragma unroll
    for (int mi = 0; mi < 4; mi++) {
#pragma unroll
        for (int ni = 0; ni < 4; ni++) {
            int row = rowBase + wr + mi * 16 + gg;
            int col = wc + ni * 8 + cq;
            float2 v0 = { acc[mi][ni][0], acc[mi][ni][1] };
            float2 v1 = { acc[mi][ni][2], acc[mi][ni][3] };
            *(float2*)(o + (size_t)row * DD + col)       = v0;
            *(float2*)(o + (size_t)(row + 8) * DD + col) = v1;
        }
    }
}

// ---------------------------------------------------------------------------
extern "C" void kernel_launch(void* const* d_in, const int* in_sizes, int n_in,
                              void* d_out, int out_size)
{
    const float* Q = (const float*)d_in[0];
    const float* K = (const float*)d_in[1];
    const float* V = (const float*)d_in[2];

    float* O = (float*)d_out;
    float* W = (float*)d_out + (size_t)NHEAD * SS * DD;

    cudaFuncSetAttribute(qk_kernel, cudaFuncAttributeMaxDynamicSharedMemorySize, QK_SMEM);
    cudaFuncSetAttribute(pv_kernel, cudaFuncAttributeMaxDynamicSharedMemorySize, PV_SMEM);

    prep_all<<<16384, 256>>>(Q, K, V);
    qk_kernel<<<dim3(SS / 128, SS / 128, NHEAD), 256, QK_SMEM>>>(W);
    pv_kernel<<<dim3(SS / 128, NHEAD), 256, PV_SMEM>>>(W, O);
}

// round 13
// speedup vs baseline: 1.4474x; 1.4474x over previous
#include <cuda_runtime.h>
#include <cuda_bf16.h>
#include <cstdint>

#define SS     2048
#define DD     128
#define NHEAD  32
#define SCALE  0.08838834764831845f
#define CH     32
#define SA2    40
#define PLANE_B (128 * SA2 * 2)

__device__ __nv_bfloat16 g_Qhi[(size_t)NHEAD * SS * DD];
__device__ __nv_bfloat16 g_Qlo[(size_t)NHEAD * SS * DD];
__device__ __nv_bfloat16 g_Khi[(size_t)NHEAD * SS * DD];
__device__ __nv_bfloat16 g_Klo[(size_t)NHEAD * SS * DD];
__device__ __nv_bfloat16 g_Vthi[(size_t)NHEAD * DD * SS];
__device__ __nv_bfloat16 g_Vtlo[(size_t)NHEAD * DD * SS];
__device__ float g_part[(size_t)NHEAD * SS * 16];

// ---------------------------------------------------------------------------
__device__ __forceinline__ unsigned smem_u32(const void* p)
{
    return (unsigned)__cvta_generic_to_shared(p);
}

__device__ __forceinline__ void split_pack(float f0, float f1,
                                           unsigned& hi, unsigned& lo)
{
    __nv_bfloat162 h;
    h.x = __float2bfloat16(f0);
    h.y = __float2bfloat16(f1);
    __nv_bfloat162 l;
    l.x = __float2bfloat16(f0 - __bfloat162float(h.x));
    l.y = __float2bfloat16(f1 - __bfloat162float(h.y));
    hi = *reinterpret_cast<unsigned*>(&h);
    lo = *reinterpret_cast<unsigned*>(&l);
}

__device__ __forceinline__ void ldsm_x4(unsigned& r0, unsigned& r1,
                                        unsigned& r2, unsigned& r3,
                                        unsigned addr)
{
    asm volatile("ldmatrix.sync.aligned.m8n8.x4.shared.b16 {%0,%1,%2,%3}, [%4];"
                 : "=r"(r0), "=r"(r1), "=r"(r2), "=r"(r3) : "r"(addr));
}

__device__ __forceinline__ void mma_bf16(float* c, const unsigned* a,
                                         const unsigned* b)
{
    asm volatile(
        "mma.sync.aligned.m16n8k16.row.col.f32.bf16.bf16.f32 "
        "{%0,%1,%2,%3}, {%4,%5,%6,%7}, {%8,%9}, {%0,%1,%2,%3};"
        : "+f"(c[0]), "+f"(c[1]), "+f"(c[2]), "+f"(c[3])
        : "r"(a[0]), "r"(a[1]), "r"(a[2]), "r"(a[3]),
          "r"(b[0]), "r"(b[1]));
}

// streaming (evict-first) global access helpers
__device__ __forceinline__ float4 ldg_cs4(const float* p)
{
    float4 v;
    asm volatile("ld.global.cs.v4.f32 {%0,%1,%2,%3}, [%4];"
                 : "=f"(v.x), "=f"(v.y), "=f"(v.z), "=f"(v.w) : "l"(p));
    return v;
}
__device__ __forceinline__ void stg_cs4(float* p, float4 v)
{
    asm volatile("st.global.cs.v4.f32 [%0], {%1,%2,%3,%4};"
                 :: "l"(p), "f"(v.x), "f"(v.y), "f"(v.z), "f"(v.w));
}
__device__ __forceinline__ void stg_cs2(float* p, float2 v)
{
    asm volatile("st.global.cs.v2.f32 [%0], {%1,%2};"
                 :: "l"(p), "f"(v.x), "f"(v.y));
}

#define CP16(dst, src) \
    asm volatile("cp.async.cg.shared.global [%0], [%1], 16;" :: "r"(dst), "l"(src))
#define CP_COMMIT  asm volatile("cp.async.commit_group;")
#define CP_WAIT1   asm volatile("cp.async.wait_group 1;")
#define CP_WAIT0   asm volatile("cp.async.wait_group 0;")

struct LaneOff { int a[4]; int b[2]; };

__device__ __forceinline__ LaneOff make_off(int warp, int lane)
{
    const int wr = (warp >> 2) * 64;
    const int wc = (warp & 3) * 32;
    const int rA = (lane & 7) + ((lane >> 3) & 1) * 8;
    const int cA = (lane >> 4) * 8;
    const int rB = (lane & 7) + (lane >> 4) * 8;
    const int cB = ((lane >> 3) & 1) * 8;
    LaneOff o;
#pragma unroll
    for (int mi = 0; mi < 4; mi++) o.a[mi] = ((wr + mi * 16 + rA) * SA2 + cA) * 2;
#pragma unroll
    for (int np = 0; np < 2; np++) o.b[np] = ((wc + np * 16 + rB) * SA2 + cB) * 2;
    return o;
}

__device__ __forceinline__ void mma_chunk(
    unsigned aHiB, unsigned aLoB, unsigned bHiB, unsigned bLoB,
    const LaneOff& o, float acc[4][4][4])
{
#pragma unroll
    for (int ks = 0; ks < 2; ks++) {
        const unsigned off = ks * 32;
        unsigned bh[4][2], bl[4][2];
        ldsm_x4(bh[0][0], bh[0][1], bh[1][0], bh[1][1], bHiB + o.b[0] + off);
        ldsm_x4(bh[2][0], bh[2][1], bh[3][0], bh[3][1], bHiB + o.b[1] + off);
        ldsm_x4(bl[0][0], bl[0][1], bl[1][0], bl[1][1], bLoB + o.b[0] + off);
        ldsm_x4(bl[2][0], bl[2][1], bl[3][0], bl[3][1], bLoB + o.b[1] + off);
#pragma unroll
        for (int mi = 0; mi < 4; mi++) {
            unsigned ah[4], al[4];
            ldsm_x4(ah[0], ah[1], ah[2], ah[3], aHiB + o.a[mi] + off);
            ldsm_x4(al[0], al[1], al[2], al[3], aLoB + o.a[mi] + off);
#pragma unroll
            for (int ni = 0; ni < 4; ni++) {
                mma_bf16(acc[mi][ni], ah, bh[ni]);
                mma_bf16(acc[mi][ni], ah, bl[ni]);
                mma_bf16(acc[mi][ni], al, bh[ni]);
            }
        }
    }
}

// ---------------------------------------------------------------------------
__global__ __launch_bounds__(256) void prep_all(
    const float* __restrict__ Q, const float* __restrict__ K,
    const float* __restrict__ V)
{
    __shared__ float T[32][33];
    if (blockIdx.x < 8192) {
        size_t idx = (size_t)blockIdx.x * 256 + threadIdx.x;
        float4 qv = ((const float4*)Q)[idx];
        unsigned h0, l0, h1, l1;
        split_pack(qv.x * SCALE, qv.y * SCALE, h0, l0);
        split_pack(qv.z * SCALE, qv.w * SCALE, h1, l1);
        ((uint2*)g_Qhi)[idx] = make_uint2(h0, h1);
        ((uint2*)g_Qlo)[idx] = make_uint2(l0, l1);
        float4 kv = ((const float4*)K)[idx];
        split_pack(kv.x, kv.y, h0, l0);
        split_pack(kv.z, kv.w, h1, l1);
        ((uint2*)g_Khi)[idx] = make_uint2(h0, h1);
        ((uint2*)g_Klo)[idx] = make_uint2(l0, l1);
    } else {
        int b    = blockIdx.x - 8192;
        int k0   = (b & 63) * 32;
        int d0   = ((b >> 6) & 3) * 32;
        int head = b >> 8;
        const int tid = threadIdx.x;
        const float* v = V + (size_t)head * SS * DD;
#pragma unroll
        for (int p = 0; p < 4; p++) {
            int kl = (tid >> 5) + p * 8;
            int dl = tid & 31;
            T[dl][kl] = v[(size_t)(k0 + kl) * DD + d0 + dl];
        }
        __syncthreads();
#pragma unroll
        for (int p = 0; p < 4; p++) {
            int dl = (tid >> 5) + p * 8;
            int kl = tid & 31;
            float f = T[dl][kl];
            __nv_bfloat16 h = __float2bfloat16(f);
            __nv_bfloat16 l = __float2bfloat16(f - __bfloat162float(h));
            size_t out = ((size_t)head * DD + d0 + dl) * SS + k0 + kl;
            g_Vthi[out] = h;
            g_Vtlo[out] = l;
        }
    }
}

// ---------------------------------------------------------------------------
// Kernel A: W = exp(Q' @ K^T), per-row partial sums -> g_part. (round-11 form,
// W stores streamed with .cs to protect plane data in L2)
// ---------------------------------------------------------------------------
#define QK_STAGE_B (4 * PLANE_B)
#define QK_SMEM    (2 * QK_STAGE_B)

__global__ __launch_bounds__(256, 2) void qk_kernel(float* __restrict__ W)
{
    extern __shared__ __nv_bfloat16 smb[];
    __shared__ float part_sm[128 * 4];
    const unsigned base = smem_u32(smb);

    const int tid  = threadIdx.x;
    const int lane = tid & 31;
    const int warp = tid >> 5;
    const int head = blockIdx.z;
    const int rowBase = blockIdx.y * 128;
    const int colBase = blockIdx.x * 128;

    float* w = W + (size_t)head * SS * SS;

    const size_t qoff = ((size_t)head * SS + rowBase) * DD;
    const size_t koff = ((size_t)head * SS + colBase) * DD;
    const __nv_bfloat16* srcP[8];
    unsigned dstOff[8];
#pragma unroll
    for (int i = 0; i < 8; i++) {
        int idx = tid + i * 256;
        int seg = idx & 3;
        int r   = (idx >> 2) & 127;
        int pl  = idx >> 9;
        const __nv_bfloat16* bp =
            pl == 0 ? g_Qhi + qoff : pl == 1 ? g_Qlo + qoff :
            pl == 2 ? g_Khi + koff : g_Klo + koff;
        srcP[i]   = bp + (size_t)r * DD + seg * 8;
        dstOff[i] = pl * PLANE_B + r * (SA2 * 2) + seg * 16;
    }

    const LaneOff lo = make_off(warp, lane);

    float acc[4][4][4];
#pragma unroll
    for (int mi = 0; mi < 4; mi++)
#pragma unroll
        for (int ni = 0; ni < 4; ni++)
#pragma unroll
            for (int t = 0; t < 4; t++) acc[mi][ni][t] = 0.0f;

#pragma unroll
    for (int i = 0; i < 8; i++)
        CP16(base + dstOff[i], srcP[i]);
    CP_COMMIT;

    const int NCH = DD / CH;   // 4
#pragma unroll
    for (int c = 0; c < NCH; c++) {
        __syncthreads();
        if (c + 1 < NCH) {
            const unsigned sb = base + ((c + 1) & 1) * QK_STAGE_B;
#pragma unroll
            for (int i = 0; i < 8; i++)
                CP16(sb + dstOff[i], srcP[i] + (c + 1) * CH);
            CP_COMMIT;
            CP_WAIT1;
        } else {
            CP_WAIT0;
        }
        __syncthreads();

        const unsigned st = base + (c & 1) * QK_STAGE_B;
        mma_chunk(st, st + PLANE_B, st + 2 * PLANE_B, st + 3 * PLANE_B, lo, acc);
    }

    const int wr = (warp >> 2) * 64;
    const int wc = (warp & 3) * 32;
    const int gg = lane >> 2;
    const int cq = (lane & 3) * 2;

#pragma unroll
    for (int mi = 0; mi < 4; mi++) {
        float s0 = 0.0f, s1 = 0.0f;
#pragma unroll
        for (int ni = 0; ni < 4; ni++) {
            acc[mi][ni][0] = __expf(acc[mi][ni][0]);
            acc[mi][ni][1] = __expf(acc[mi][ni][1]);
            acc[mi][ni][2] = __expf(acc[mi][ni][2]);
            acc[mi][ni][3] = __expf(acc[mi][ni][3]);
            s0 += acc[mi][ni][0] + acc[mi][ni][1];
            s1 += acc[mi][ni][2] + acc[mi][ni][3];
        }
        s0 += __shfl_xor_sync(0xffffffffu, s0, 1);
        s0 += __shfl_xor_sync(0xffffffffu, s0, 2);
        s1 += __shfl_xor_sync(0xffffffffu, s1, 1);
        s1 += __shfl_xor_sync(0xffffffffu, s1, 2);
        if ((lane & 3) == 0) {
            part_sm[(wr + mi * 16 + gg) * 4 + (warp & 3)]     = s0;
            part_sm[(wr + mi * 16 + gg + 8) * 4 + (warp & 3)] = s1;
        }
    }

#pragma unroll
    for (int mi = 0; mi < 4; mi++) {
#pragma unroll
        for (int ni = 0; ni < 4; ni++) {
            int row = rowBase + wr + mi * 16 + gg;
            int col = colBase + wc + ni * 8 + cq;
            float2 v0 = { acc[mi][ni][0], acc[mi][ni][1] };
            float2 v1 = { acc[mi][ni][2], acc[mi][ni][3] };
            stg_cs2(w + (size_t)row * SS + col,       v0);
            stg_cs2(w + (size_t)(row + 8) * SS + col, v1);
        }
    }

    __syncthreads();
    if (tid < 128) {
        float s = part_sm[tid * 4 + 0] + part_sm[tid * 4 + 1]
                + part_sm[tid * 4 + 2] + part_sm[tid * 4 + 3];
        g_part[((size_t)head * SS + rowBase + tid) * 16 + blockIdx.x] = s;
    }
}

// ---------------------------------------------------------------------------
// Kernel C: O = P @ V ; normalizes W in place. Round-11 structure +
// P LDG hoisted above the V wait + streaming hints on P load / W store.
// ---------------------------------------------------------------------------
#define PV_PPL   0
#define PV_PBUF  (2 * PLANE_B)
#define PV_VST   (2 * PV_PBUF)
#define PV_VSTG  (2 * PLANE_B)
#define PV_SMEM  (PV_VST + 2 * PV_VSTG)

__global__ __launch_bounds__(256, 2) void pv_kernel(
    float* P, float* __restrict__ O)
{
    extern __shared__ __nv_bfloat16 smb[];
    const unsigned base = smem_u32(smb);

    const int tid  = threadIdx.x;
    const int lane = tid & 31;
    const int warp = tid >> 5;
    const int head = blockIdx.y;
    const int rowBase = blockIdx.x * 128;
    const int wc   = (warp & 3) * 32;

    float* p = P + (size_t)head * SS * SS;
    float* o = O + (size_t)head * SS * DD;

    float* pptr[4];
    unsigned pElem[4];
    float inv[4];
#pragma unroll
    for (int i = 0; i < 4; i++) {
        int idx = tid + i * 256;
        int seg = idx & 7;
        int r   = idx >> 3;
        pptr[i]  = p + (size_t)(rowBase + r) * SS + seg * 4;
        pElem[i] = r * SA2 + seg * 4;
        const float4* gp = (const float4*)&g_part[((size_t)head * SS + rowBase + r) * 16];
        float4 a = gp[0], b = gp[1], c = gp[2], d = gp[3];
        float s = ((a.x + a.y) + (a.z + a.w)) + ((b.x + b.y) + (b.z + b.w))
                + ((c.x + c.y) + (c.z + c.w)) + ((d.x + d.y) + (d.z + d.w));
        inv[i] = 1.0f / s;
    }

    const __nv_bfloat16* vhi = g_Vthi + (size_t)head * DD * SS;
    const __nv_bfloat16* vlo = g_Vtlo + (size_t)head * DD * SS;

    auto load_v = [&](int c, int stage) {
        const unsigned vb = base + PV_VST + stage * PV_VSTG;
#pragma unroll
        for (int j = 0; j < 8; j++) {
            int idx = lane + 32 * j;
            int seg = idx & 3;
            int r   = (idx >> 2) & 31;
            int pl  = idx >> 7;
            const __nv_bfloat16* s =
                (pl ? vlo : vhi) + (size_t)(wc + r) * SS + c * CH + seg * 8;
            unsigned d = vb + pl * PLANE_B + (wc + r) * (SA2 * 2) + seg * 16;
            CP16(d, s);
        }
        CP_COMMIT;
    };

    const LaneOff lof = make_off(warp, lane);

    float acc[4][4][4];
#pragma unroll
    for (int mi = 0; mi < 4; mi++)
#pragma unroll
        for (int ni = 0; ni < 4; ni++)
#pragma unroll
            for (int t = 0; t < 4; t++) acc[mi][ni][t] = 0.0f;

    // prologue
    load_v(0, 0);
    {
        __nv_bfloat16* phi = smb + PV_PPL / 2;
        __nv_bfloat16* plo = phi + PLANE_B / 2;
#pragma unroll
        for (int i = 0; i < 4; i++) {
            float4 f = ldg_cs4(pptr[i]);
            f.x *= inv[i]; f.y *= inv[i]; f.z *= inv[i]; f.w *= inv[i];
            stg_cs4(pptr[i], f);
            unsigned h0, l0, h1, l1;
            split_pack(f.x, f.y, h0, l0);
            split_pack(f.z, f.w, h1, l1);
            *(uint2*)(phi + pElem[i]) = make_uint2(h0, h1);
            *(uint2*)(plo + pElem[i]) = make_uint2(l0, l1);
        }
    }
    __syncthreads();

    const int NCH = SS / CH;   // 64
    for (int c = 0; c < NCH; c++) {
        // issue next V chunk, then prefetch next P chunk BEFORE waiting on V
        float4 n4[4];
        if (c + 1 < NCH) {
            load_v(c + 1, (c + 1) & 1);
#pragma unroll
            for (int i = 0; i < 4; i++)
                n4[i] = ldg_cs4(pptr[i] + (c + 1) * CH);
            CP_WAIT1;
        } else {
            CP_WAIT0;
        }

        const unsigned pb = base + PV_PPL + (c & 1) * PV_PBUF;
        const unsigned vb = base + PV_VST + (c & 1) * PV_VSTG;
        mma_chunk(pb, pb + PLANE_B, vb, vb + PLANE_B, lof, acc);

        if (c + 1 < NCH) {
            __nv_bfloat16* phi = smb + (PV_PPL + ((c + 1) & 1) * PV_PBUF) / 2;
            __nv_bfloat16* plo = phi + PLANE_B / 2;
#pragma unroll
            for (int i = 0; i < 4; i++) {
                float4 f = n4[i];
                f.x *= inv[i]; f.y *= inv[i]; f.z *= inv[i]; f.w *= inv[i];
                stg_cs4(pptr[i] + (c + 1) * CH, f);
                unsigned h0, l0, h1, l1;
                split_pack(f.x, f.y, h0, l0);
                split_pack(f.z, f.w, h1, l1);
                *(uint2*)(phi + pElem[i]) = make_uint2(h0, h1);
                *(uint2*)(plo + pElem[i]) = make_uint2(l0, l1);
            }
        }
        __syncthreads();
    }

    const int wr = (warp >> 2) * 64;
    const int gg = lane >> 2;
    const int cq = (lane & 3) * 2;
#pragma unroll
    for (int mi = 0; mi < 4; mi++) {
#pragma unroll
        for (int ni = 0; ni < 4; ni++) {
            int row = rowBase + wr + mi * 16 + gg;
            int col = wc + ni * 8 + cq;
            float2 v0 = { acc[mi][ni][0], acc[mi][ni][1] };
            float2 v1 = { acc[mi][ni][2], acc[mi][ni][3] };
            *(float2*)(o + (size_t)row * DD + col)       = v0;
            *(float2*)(o + (size_t)(row + 8) * DD + col) = v1;
        }
    }
}

// ---------------------------------------------------------------------------
extern "C" void kernel_launch(void* const* d_in, const int* in_sizes, int n_in,
                              void* d_out, int out_size)
{
    const float* Q = (const float*)d_in[0];
    const float* K = (const float*)d_in[1];
    const float* V = (const float*)d_in[2];

    float* O = (float*)d_out;
    float* W = (float*)d_out + (size_t)NHEAD * SS * DD;

    cudaFuncSetAttribute(qk_kernel, cudaFuncAttributeMaxDynamicSharedMemorySize, QK_SMEM);
    cudaFuncSetAttribute(pv_kernel, cudaFuncAttributeMaxDynamicSharedMemorySize, PV_SMEM);

    prep_all<<<16384, 256>>>(Q, K, V);
    qk_kernel<<<dim3(SS / 128, SS / 128, NHEAD), 256, QK_SMEM>>>(W);
    pv_kernel<<<dim3(SS / 128, NHEAD), 256, PV_SMEM>>>(W, O);
}